// round 2
// baseline (speedup 1.0000x reference)
#include <cuda_runtime.h>
#include <cuda_bf16.h>

#define N_NODES 50000
#define D_FEAT  128

// Row offsets into the sorted edge list (CSR row_ptr). 50001 ints.
__device__ int g_offsets[N_NODES + 1];

// Kernel A: offsets[i] = lower_bound(edge_src, i) over sorted int32 edge_src.
__global__ void build_offsets_kernel(const int* __restrict__ edge_src, int n_edges) {
    int i = blockIdx.x * blockDim.x + threadIdx.x;
    if (i > N_NODES) return;
    int key = i;
    int lo = 0, hi = n_edges;
    while (lo < hi) {
        int mid = (lo + hi) >> 1;
        if (edge_src[mid] < key) lo = mid + 1;
        else hi = mid;
    }
    g_offsets[i] = lo;
}

// Kernel B: one warp per node. acc = x[i]; for e in [row_ptr[i], row_ptr[i+1]):
// acc += x[edge_dst[e]]. Each lane holds one float4 (4 feats), 32 lanes = 128.
__global__ void graph_pool_kernel(const float4* __restrict__ x,
                                  const int* __restrict__ edge_dst,
                                  float4* __restrict__ out) {
    int warp_id = (blockIdx.x * blockDim.x + threadIdx.x) >> 5;
    int lane = threadIdx.x & 31;
    if (warp_id >= N_NODES) return;

    int beg = g_offsets[warp_id];
    int end = g_offsets[warp_id + 1];

    // self feature
    float4 acc = x[(size_t)warp_id * 32 + lane];

    int e = beg;
    // 4-way unroll: 4 independent 512B row-gathers in flight per warp (MLP)
    for (; e + 4 <= end; e += 4) {
        int d0 = edge_dst[e + 0];
        int d1 = edge_dst[e + 1];
        int d2 = edge_dst[e + 2];
        int d3 = edge_dst[e + 3];
        float4 v0 = __ldg(&x[(size_t)d0 * 32 + lane]);
        float4 v1 = __ldg(&x[(size_t)d1 * 32 + lane]);
        float4 v2 = __ldg(&x[(size_t)d2 * 32 + lane]);
        float4 v3 = __ldg(&x[(size_t)d3 * 32 + lane]);
        acc.x += v0.x; acc.y += v0.y; acc.z += v0.z; acc.w += v0.w;
        acc.x += v1.x; acc.y += v1.y; acc.z += v1.z; acc.w += v1.w;
        acc.x += v2.x; acc.y += v2.y; acc.z += v2.z; acc.w += v2.w;
        acc.x += v3.x; acc.y += v3.y; acc.z += v3.z; acc.w += v3.w;
    }
    for (; e < end; e++) {
        int d = edge_dst[e];
        float4 v = __ldg(&x[(size_t)d * 32 + lane]);
        acc.x += v.x; acc.y += v.y; acc.z += v.z; acc.w += v.w;
    }

    out[(size_t)warp_id * 32 + lane] = acc;
}

extern "C" void kernel_launch(void* const* d_in, const int* in_sizes, int n_in,
                              void* d_out, int out_size) {
    const float* x = (const float*)d_in[0];
    const int* edge_src = (const int*)d_in[1];
    const int* edge_dst = (const int*)d_in[2];
    float* out = (float*)d_out;
    int n_edges = in_sizes[1];

    // Kernel A: CSR row offsets (50001 binary searches)
    {
        int threads = 256;
        int blocks = (N_NODES + 1 + threads - 1) / threads;
        build_offsets_kernel<<<blocks, threads>>>(edge_src, n_edges);
    }

    // Kernel B: one warp per node, 8 warps per block
    {
        int threads = 256;
        int warps_per_block = threads / 32;
        int blocks = (N_NODES + warps_per_block - 1) / warps_per_block;
        graph_pool_kernel<<<blocks, threads>>>((const float4*)x, edge_dst,
                                               (float4*)out);
    }
}